// round 13
// baseline (speedup 1.0000x reference)
#include <cuda_runtime.h>
#include <cuda_fp16.h>
#include <math.h>

#define EMB 64
#define RNN 128
#define BB  512
#define LL  256
#define KK  18
#define G   8
#define ZC  512   // 4*RNN
#define VOCAB 30001
#define PBR 32    // vocab rows per pbuild block
#define LR  28    // (b,t) rows per logits block

// Scratch (static device allocations; no cudaMalloc allowed)
// g_P2[dir][v][u] = {half2(z_i, z_f), half2(z_g, z_o)} for hidden unit u
__device__ uint2 g_P2[2][VOCAB][RNN];                 // ~61 MB (L2-resident)
// h staging: [dir][batch-group][t][tid] = half2(h_even_batch, h_odd_batch)
__device__ unsigned int g_hstage[2][BB / G][LL][512]; // coalesced writes
__device__ float g_logits[BB][LL][KK];

typedef unsigned long long u64;
typedef unsigned int u32;

__device__ __forceinline__ u64 pk2(float lo, float hi) {
    u64 r; asm("mov.b64 %0,{%1,%2};" : "=l"(r) : "f"(lo), "f"(hi)); return r;
}
__device__ __forceinline__ void upk2(u64 v, float& lo, float& hi) {
    asm("mov.b64 {%0,%1},%2;" : "=f"(lo), "=f"(hi) : "l"(v));
}
__device__ __forceinline__ void ffma2(u64& d, u64 a, u64 b) {
    asm("fma.rn.f32x2 %0,%1,%2,%0;" : "+l"(d) : "l"(a), "l"(b));
}
__device__ __forceinline__ float fast_tanh(float x) {
    float y; asm("tanh.approx.f32 %0, %1;" : "=f"(y) : "f"(x)); return y;
}
__device__ __forceinline__ float fast_sig(float x) {
    return 0.5f * fast_tanh(0.5f * x) + 0.5f;
}
__device__ __forceinline__ u32 pack_h2(float lo, float hi) {
    __half2 v = __floats2half2_rn(lo, hi);
    return *(u32*)&v;
}
__device__ __forceinline__ float2 unpack_h2(u32 v) {
    return __half22float2(*(__half2*)&v);
}
__device__ __forceinline__ __half2 h2_of(u32 v) { return *(__half2*)&v; }
__device__ __forceinline__ u32 u_of(__half2 v) { return *(u32*)&v; }

// m16n8k16 fp16 in / fp16 accumulate (pbuild)
__device__ __forceinline__ void mma16816h(u32& c0, u32& c1,
                                          u32 a0, u32 a1, u32 a2, u32 a3,
                                          u32 b0, u32 b1) {
    asm("mma.sync.aligned.m16n8k16.row.col.f16.f16.f16.f16 "
        "{%0,%1}, {%2,%3,%4,%5}, {%6,%7}, {%0,%1};"
        : "+r"(c0), "+r"(c1)
        : "r"(a0), "r"(a1), "r"(a2), "r"(a3), "r"(b0), "r"(b1));
}
// m16n8k32 s8 / s32 accumulate (LSTM: 2x MAC per instruction)
__device__ __forceinline__ void imma32(int& d0, int& d1, int& d2, int& d3,
                                       u32 a0, u32 a1, u32 a2, u32 a3,
                                       u32 b0, u32 b1) {
    asm("mma.sync.aligned.m16n8k32.row.col.s32.s8.s8.s32 "
        "{%0,%1,%2,%3}, {%4,%5,%6,%7}, {%8,%9}, {%0,%1,%2,%3};"
        : "+r"(d0), "+r"(d1), "+r"(d2), "+r"(d3)
        : "r"(a0), "r"(a1), "r"(a2), "r"(a3), "r"(b0), "r"(b1));
}
__device__ __forceinline__ u32 pack4s8(float v0, float v1, float v2, float v3,
                                       float inv) {
    int q0 = __float2int_rn(v0 * inv), q1 = __float2int_rn(v1 * inv);
    int q2 = __float2int_rn(v2 * inv), q3 = __float2int_rn(v3 * inv);
    return (u32)(q0 & 255) | ((u32)(q1 & 255) << 8) |
           ((u32)(q2 & 255) << 16) | ((u32)(q3 & 255) << 24);
}

// ---------------------------------------------------------------------------
// Kernel 1: P2 via fp16 HMMA (unchanged from R12 win)
// ---------------------------------------------------------------------------
__global__ __launch_bounds__(256) void pbuild_kernel(
    const float* __restrict__ E,
    const float* __restrict__ Wx_f, const float* __restrict__ b_f,
    const float* __restrict__ Wx_b, const float* __restrict__ b_b)
{
    int dir = blockIdx.y;
    int r0  = blockIdx.x * PBR;
    const float* __restrict__ Wx = dir ? Wx_b : Wx_f;
    const float* __restrict__ bs = dir ? b_b : b_f;

    __shared__ __half es[PBR][EMB];
    __shared__ u32 zs[PBR][ZC / 2];

    int tid  = threadIdx.x;
    int w    = tid >> 5;
    int lane = tid & 31;
    int qr   = lane >> 2;
    int tl   = lane & 3;

    for (int i = tid; i < PBR * EMB; i += 256) {
        int r = i >> 6, e = i & 63;
        int row = r0 + r;
        int rc = (row < VOCAB) ? row : (VOCAB - 1);
        es[r][e] = __float2half(E[rc * EMB + e]);
    }

    u32 bfr[8][4][2];
#pragma unroll
    for (int nt = 0; nt < 8; nt++) {
        int n = 64 * w + 8 * nt + qr;
#pragma unroll
        for (int kt = 0; kt < 4; kt++) {
            int k0 = 16 * kt + 2 * tl;
            bfr[nt][kt][0] = pack_h2(Wx[k0 * ZC + n],       Wx[(k0 + 1) * ZC + n]);
            bfr[nt][kt][1] = pack_h2(Wx[(k0 + 8) * ZC + n], Wx[(k0 + 9) * ZC + n]);
        }
    }
    u32 binit[8];
#pragma unroll
    for (int nt = 0; nt < 8; nt++) {
        int c = 64 * w + 8 * nt + 2 * tl;
        binit[nt] = pack_h2(bs[c], bs[c + 1]);
    }
    __syncthreads();

#pragma unroll
    for (int mt = 0; mt < 2; mt++) {
        int rb = 16 * mt;
        u32 a[4][4];
#pragma unroll
        for (int kt = 0; kt < 4; kt++) {
            int k0 = 16 * kt + 2 * tl;
            a[kt][0] = *(const u32*)&es[rb + qr][k0];
            a[kt][1] = *(const u32*)&es[rb + 8 + qr][k0];
            a[kt][2] = *(const u32*)&es[rb + qr][k0 + 8];
            a[kt][3] = *(const u32*)&es[rb + 8 + qr][k0 + 8];
        }
#pragma unroll
        for (int nt = 0; nt < 8; nt++) {
            u32 c0 = binit[nt], c1 = binit[nt];
#pragma unroll
            for (int kt = 0; kt < 4; kt++)
                mma16816h(c0, c1, a[kt][0], a[kt][1], a[kt][2], a[kt][3],
                          bfr[nt][kt][0], bfr[nt][kt][1]);
            int cp = 32 * w + 4 * nt + tl;
            zs[rb + qr][cp]     = c0;
            zs[rb + 8 + qr][cp] = c1;
        }
    }
    __syncthreads();

    const __half* zh = (const __half*)zs;
    for (int i = tid; i < PBR * RNN; i += 256) {
        int r = i >> 7, u = i & 127;
        int row = r0 + r;
        if (row < VOCAB) {
            const __half* zr = zh + r * ZC;
            g_P2[dir][row][u] = make_uint2(
                u_of(__halves2half2(zr[u],       zr[u + 128])),
                u_of(__halves2half2(zr[u + 256], zr[u + 384])));
        }
    }
}

// ---------------------------------------------------------------------------
// Kernel 2: persistent LSTM via int8 IMMA m16n8k32 (2x MAC/instr).
// A = Wh^T quantized per gate-column (registers), B = h int8 (smem, n=8),
// s32 accumulate, fp32 dequant + P add in epilogue. 1 bar/step.
// ---------------------------------------------------------------------------
__global__ __launch_bounds__(512, 1) void lstm_kernel(
    const int* __restrict__ inputs,
    const float* __restrict__ Wh_f, const float* __restrict__ Wh_b)
{
    __shared__ __align__(16) u32 hA8[256];   // 4 kc x 32 lanes x 8 B, dbl-buffered
    __shared__ __align__(16) u32 hB8[256];
    __shared__ __align__(8) int2 tok2_s[LL][4];

    int dir = blockIdx.x >> 6;
    int bi  = blockIdx.x & 63;
    int b0  = bi * G;
    const float* __restrict__ Wh = dir ? Wh_b : Wh_f;
    int tid  = threadIdx.x;
    int w    = tid >> 5;
    int lane = tid & 31;
    int gm   = lane >> 2;      // qr
    int tl   = lane & 3;

    for (int i = tid; i < 256; i += 512) { hA8[i] = 0u; hB8[i] = 0u; }
    for (int i = tid; i < 4 * LL; i += 512) {
        int t = i >> 2, pr = i & 3;
        tok2_s[t][pr] = make_int2(inputs[(b0 + 2 * pr) * LL + t],
                                  inputs[(b0 + 2 * pr + 1) * LL + t]);
    }

    int u = 8 * w + gm;        // this lane's hidden unit

    // A fragments: quantize Wh per gate-column. gate g4: m-tile ti=g4>>1,
    // row (qr + 8*(g4&1)). a0=(qr,klo) a1=(qr+8,klo) a2=(qr,khi) a3=(qr+8,khi)
    float dq[4];
    u32 afr8[2][4][4];
#pragma unroll
    for (int g4 = 0; g4 < 4; g4++) {
        int o = g4 * 128 + u;
        float vals[4][8];
        float mx = 0.0f;
#pragma unroll
        for (int kc = 0; kc < 4; kc++) {
#pragma unroll
            for (int jj = 0; jj < 8; jj++) {
                int k = kc * 32 + ((jj < 4) ? (4 * tl + jj) : (16 + 4 * tl + (jj - 4)));
                float v = Wh[k * ZC + o];
                vals[kc][jj] = v;
                mx = fmaxf(mx, fabsf(v));
            }
        }
        mx = fmaxf(mx, __shfl_xor_sync(0xffffffffu, mx, 1));
        mx = fmaxf(mx, __shfl_xor_sync(0xffffffffu, mx, 2));
        float inv = (mx > 0.0f) ? (127.0f / mx) : 0.0f;
        dq[g4] = mx * (1.0f / (127.0f * 127.0f));
        int ti = g4 >> 1, rr = g4 & 1;
#pragma unroll
        for (int kc = 0; kc < 4; kc++) {
            afr8[ti][kc][rr]     = pack4s8(vals[kc][0], vals[kc][1], vals[kc][2], vals[kc][3], inv);
            afr8[ti][kc][2 + rr] = pack4s8(vals[kc][4], vals[kc][5], vals[kc][6], vals[kc][7], inv);
        }
    }
    __syncthreads();

    // B byte-write positions for (k=u, n=2tl / 2tl+1)
    int kcu = u >> 5, ru = u & 31, regu = ru >> 4, r16 = ru & 15;
    int tlp = r16 >> 2, byt = r16 & 3;
    int posE = kcu * 256 + ((2 * tl) * 4 + tlp) * 8 + regu * 4 + byt;
    int posO = posE + 32;   // n+1 -> +4*8 bytes

    u32* stage = &g_hstage[dir][bi][0][0];

    int t0 = dir ? (LL - 1) : 0;
    int2 tk = tok2_s[t0][tl];
    uint2 pE = g_P2[dir][tk.x][u];
    uint2 pO = g_P2[dir][tk.y][u];

    float c0 = 0.0f, c1 = 0.0f;

    for (int step = 0; step < LL; step++) {
        int t = dir ? (LL - 1 - step) : step;
        const u32* rd = (step & 1) ? hB8 : hA8;
        char* wb = (char*)((step & 1) ? hA8 : hB8);

        int d0[4] = {0, 0, 0, 0};
        int d1[4] = {0, 0, 0, 0};

        int tn = (step + 1 < LL) ? (dir ? t - 1 : t + 1) : t;
        tk = tok2_s[tn][tl];
        uint2 pEn = g_P2[dir][tk.x][u];
        uint2 pOn = g_P2[dir][tk.y][u];

#pragma unroll
        for (int kc = 0; kc < 4; kc++) {
            uint2 bb = *(const uint2*)&rd[kc * 64 + lane * 2];
            imma32(d0[0], d0[1], d0[2], d0[3],
                   afr8[0][kc][0], afr8[0][kc][1], afr8[0][kc][2], afr8[0][kc][3],
                   bb.x, bb.y);
            imma32(d1[0], d1[1], d1[2], d1[3],
                   afr8[1][kc][0], afr8[1][kc][1], afr8[1][kc][2], afr8[1][kc][3],
                   bb.x, bb.y);
        }

        // dequant + P add (fp32): tile0 rows = gates i(f via +8row); tile1 = g,o
        float2 pEif = unpack_h2(pE.x), pEgo = unpack_h2(pE.y);
        float2 pOif = unpack_h2(pO.x), pOgo = unpack_h2(pO.y);
        float ziE = (float)d0[0] * dq[0] + pEif.x;
        float ziO = (float)d0[1] * dq[0] + pOif.x;
        float zfE = (float)d0[2] * dq[1] + pEif.y;
        float zfO = (float)d0[3] * dq[1] + pOif.y;
        float zgE = (float)d1[0] * dq[2] + pEgo.x;
        float zgO = (float)d1[1] * dq[2] + pOgo.x;
        float zoE = (float)d1[2] * dq[3] + pEgo.y;
        float zoO = (float)d1[3] * dq[3] + pOgo.y;

        c0 = fast_sig(zfE) * c0 + fast_sig(ziE) * fast_tanh(zgE);
        float hE = fast_sig(zoE) * fast_tanh(c0);
        c1 = fast_sig(zfO) * c1 + fast_sig(ziO) * fast_tanh(zgO);
        float hO = fast_sig(zoO) * fast_tanh(c1);

        wb[posE] = (char)__float2int_rn(hE * 127.0f);
        wb[posO] = (char)__float2int_rn(hO * 127.0f);
        stage[t * 512 + tid] = pack_h2(hE, hO);
        pE = pEn; pO = pOn;
        __syncthreads();
    }
}

// ---------------------------------------------------------------------------
// Kernel 3: logits (unchanged)
// ---------------------------------------------------------------------------
__global__ __launch_bounds__(512) void logits_kernel(
    const float* __restrict__ Wd, const float* __restrict__ bd)
{
    __shared__ __align__(16) float h_s[LR][2 * RNN];
    __shared__ __align__(16) float2 Wt2[KK][RNN + 1];
    __shared__ float bd_s[KK];

    int tid = threadIdx.x;
    int bt0 = blockIdx.x * LR;

    for (int i = tid; i < KK * RNN; i += 512) {
        int k = i / RNN, e2 = i % RNN;
        Wt2[k][e2] = make_float2(Wd[(2 * e2) * KK + k], Wd[(2 * e2 + 1) * KK + k]);
    }
    if (tid < KK) bd_s[tid] = bd[tid];
    for (int i = tid; i < LR * 2 * RNN; i += 512) {
        int r = i >> 8, e = i & 255;
        int bt = bt0 + r;
        if (bt < BB * LL) {
            int b = bt >> 8, t = bt & 255;
            int dir = e >> 7, uu = e & 127;
            u32 v = g_hstage[dir][b >> 3][t][(uu >> 3) * 32 + (uu & 7) * 4 + ((b & 7) >> 1)];
            float2 hv = unpack_h2(v);
            h_s[r][e] = (b & 1) ? hv.y : hv.x;
        }
    }
    __syncthreads();

    if (tid >= LR * KK) return;
    int r = tid / KK, k = tid % KK;
    int bt = bt0 + r;
    if (bt >= BB * LL) return;

    u64 acc = 0;
    const u64* hp = (const u64*)&h_s[r][0];
    const u64* wp = (const u64*)&Wt2[k][0];
#pragma unroll 8
    for (int e2 = 0; e2 < RNN; e2++) ffma2(acc, hp[e2], wp[e2]);

    float lo, hi; upk2(acc, lo, hi);
    int b = bt >> 8, t = bt & 255;
    g_logits[b][t][k] = lo + hi + bd_s[k];
}

// ---------------------------------------------------------------------------
// Kernel 4: CRF. 2 rows/warp (chain interleave) x 2 warps/block -> 128 blocks
// (full-chip occupancy restored). Tree-split sum, expT trick, logit prefetch.
// ---------------------------------------------------------------------------
__global__ __launch_bounds__(64) void crf_kernel(
    const int* __restrict__ labels, const float* __restrict__ T,
    float* __restrict__ out, int out_size)
{
    if (blockIdx.x == BB / 4) {
        for (int i = threadIdx.x; i < KK * KK; i += 64)
            if ((BB + i) < out_size) out[BB + i] = T[i];
        return;
    }

    __shared__ float T_s[KK * KK];
    __shared__ float expT_s[KK][KK];
    int tid = threadIdx.x;
    for (int i = tid; i < KK * KK; i += 64) {
        float tv = T[i];
        T_s[i] = tv;
        expT_s[i / KK][i % KK] = __expf(tv);
    }
    __syncthreads();

    int warp = tid >> 5;
    int lane = tid & 31;
    int bA = (blockIdx.x * 2 + warp) * 2;
    int bB = bA + 1;
    if (bA >= BB) return;

    const int* labA = labels + bA * LL;
    const int* labB = labels + bB * LL;

    int cA = 0, cB2 = 0;
    for (int l = lane; l < LL; l += 32) {
        cA  += (labA[l] != 0);
        cB2 += (labB[l] != 0);
    }
#pragma unroll
    for (int off = 16; off; off >>= 1) {
        cA  += __shfl_xor_sync(0xffffffffu, cA, off);
        cB2 += __shfl_xor_sync(0xffffffffu, cB2, off);
    }
    int lenA = cA, lenB = cB2;

    float usA = 0.0f, bsA = 0.0f, usB = 0.0f, bsB = 0.0f;
    for (int l = lane; l < LL; l += 32) {
        int yA = labA[l], yB = labB[l];
        if (l < lenA) usA += g_logits[bA][l][yA];
        if (l >= 1 && l < lenA) bsA += T_s[labA[l - 1] * KK + yA];
        if (l < lenB) usB += g_logits[bB][l][yB];
        if (l >= 1 && l < lenB) bsB += T_s[labB[l - 1] * KK + yB];
    }
#pragma unroll
    for (int off = 16; off; off >>= 1) {
        usA += __shfl_xor_sync(0xffffffffu, usA, off);
        bsA += __shfl_xor_sync(0xffffffffu, bsA, off);
        usB += __shfl_xor_sync(0xffffffffu, usB, off);
        bsB += __shfl_xor_sync(0xffffffffu, bsB, off);
    }

    int k = (lane < KK) ? lane : 0;
    float alA = (lane < KK) ? g_logits[bA][0][k] : -1e30f;
    float alB = (lane < KK) ? g_logits[bB][0][k] : -1e30f;
    float lgA = g_logits[bA][1][k];
    float lgB = g_logits[bB][1][k];

    for (int l = 1; l < LL; l++) {
        float lgA2 = (l + 1 < LL) ? g_logits[bA][l + 1][k] : 0.0f;
        float lgB2 = (l + 1 < LL) ? g_logits[bB][l + 1][k] : 0.0f;
        float a0A = __shfl_sync(0xffffffffu, alA, 0);
        float a0B = __shfl_sync(0xffffffffu, alB, 0);
        float eA = (lane < KK) ? __expf(alA - a0A) : 0.0f;
        float eB = (lane < KK) ? __expf(alB - a0B) : 0.0f;
        float sA0 = 0.f, sA1 = 0.f, sA2 = 0.f;
        float sB0 = 0.f, sB1 = 0.f, sB2 = 0.f;
#pragma unroll
        for (int k1 = 0; k1 < 6; k1++) {
            sA0 = fmaf(__shfl_sync(0xffffffffu, eA, k1),      expT_s[k1][k],      sA0);
            sA1 = fmaf(__shfl_sync(0xffffffffu, eA, k1 + 6),  expT_s[k1 + 6][k],  sA1);
            sA2 = fmaf(__shfl_sync(0xffffffffu, eA, k1 + 12), expT_s[k1 + 12][k], sA2);
            sB0 = fmaf(__shfl_sync(0xffffffffu, eB, k1),      expT_s[k1][k],      sB0);
            sB1 = fmaf(__shfl_sync(0xffffffffu, eB, k1 + 6),  expT_s[k1 + 6][k],  sB1);
            sB2 = fmaf(__shfl_sync(0xffffffffu, eB, k1 + 12), expT_s[k1 + 12][k], sB2);
        }
        float naA = a0A + __logf((sA0 + sA1) + sA2) + lgA;
        float naB = a0B + __logf((sB0 + sB1) + sB2) + lgB;
        if (lane < KK && l < lenA) alA = naA;
        if (lane < KK && l < lenB) alB = naB;
        lgA = lgA2;
        lgB = lgB2;
    }

    float mA = alA, mB = alB;
#pragma unroll
    for (int off = 16; off; off >>= 1) {
        mA = fmaxf(mA, __shfl_xor_sync(0xffffffffu, mA, off));
        mB = fmaxf(mB, __shfl_xor_sync(0xffffffffu, mB, off));
    }
    float esA = (lane < KK) ? __expf(alA - mA) : 0.0f;
    float esB = (lane < KK) ? __expf(alB - mB) : 0.0f;
#pragma unroll
    for (int off = 16; off; off >>= 1) {
        esA += __shfl_xor_sync(0xffffffffu, esA, off);
        esB += __shfl_xor_sync(0xffffffffu, esB, off);
    }
    if (lane == 0) {
        if (bA < out_size) out[bA] = usA + bsA - (mA + __logf(esA));
        if (bB < out_size) out[bB] = usB + bsB - (mB + __logf(esB));
    }
}

// ---------------------------------------------------------------------------
extern "C" void kernel_launch(void* const* d_in, const int* in_sizes, int n_in,
                              void* d_out, int out_size)
{
    const int*   inputs = (const int*)  d_in[0];
    const int*   labels = (const int*)  d_in[1];
    const float* E      = (const float*)d_in[2];
    const float* Wx_f   = (const float*)d_in[3];
    const float* Wh_f   = (const float*)d_in[4];
    const float* b_f    = (const float*)d_in[5];
    const float* Wx_b   = (const float*)d_in[6];
    const float* Wh_b   = (const float*)d_in[7];
    const float* b_b    = (const float*)d_in[8];
    const float* Wd     = (const float*)d_in[9];
    const float* bd     = (const float*)d_in[10];
    const float* T      = (const float*)d_in[11];
    float* out = (float*)d_out;

    dim3 pg((VOCAB + PBR - 1) / PBR, 2);
    pbuild_kernel<<<pg, 256>>>(E, Wx_f, b_f, Wx_b, b_b);
    lstm_kernel<<<128, 512>>>(inputs, Wh_f, Wh_b);
    int nbt = BB * LL;
    logits_kernel<<<(nbt + LR - 1) / LR, 512>>>(Wd, bd);
    crf_kernel<<<BB / 4 + 1, 64>>>(labels, T, out, out_size);
}

// round 14
// speedup vs baseline: 1.2973x; 1.2973x over previous
#include <cuda_runtime.h>
#include <cuda_fp16.h>
#include <math.h>

#define EMB 64
#define RNN 128
#define BB  512
#define LL  256
#define KK  18
#define G   8
#define ZC  512   // 4*RNN
#define VOCAB 30001
#define PBR 32    // vocab rows per pbuild block
#define LR  28    // (b,t) rows per logits block

// Scratch (static device allocations; no cudaMalloc allowed)
// g_P2[dir][v][u] = {half2(z_i, z_f), half2(z_g, z_o)} for hidden unit u
__device__ uint2 g_P2[2][VOCAB][RNN];                 // ~61 MB (L2-resident)
// h staging: [dir][batch-group][t][tid] = half2(h_even_batch, h_odd_batch)
__device__ unsigned int g_hstage[2][BB / G][LL][512]; // coalesced writes
__device__ float g_logits[BB][LL][KK];

typedef unsigned long long u64;
typedef unsigned int u32;

__device__ __forceinline__ u64 pk2(float lo, float hi) {
    u64 r; asm("mov.b64 %0,{%1,%2};" : "=l"(r) : "f"(lo), "f"(hi)); return r;
}
__device__ __forceinline__ void upk2(u64 v, float& lo, float& hi) {
    asm("mov.b64 {%0,%1},%2;" : "=f"(lo), "=f"(hi) : "l"(v));
}
__device__ __forceinline__ void ffma2(u64& d, u64 a, u64 b) {
    asm("fma.rn.f32x2 %0,%1,%2,%0;" : "+l"(d) : "l"(a), "l"(b));
}
__device__ __forceinline__ float fast_tanh(float x) {
    float y; asm("tanh.approx.f32 %0, %1;" : "=f"(y) : "f"(x)); return y;
}
__device__ __forceinline__ float fast_sig(float x) {
    return 0.5f * fast_tanh(0.5f * x) + 0.5f;
}
__device__ __forceinline__ u32 pack_h2(float lo, float hi) {
    __half2 v = __floats2half2_rn(lo, hi);
    return *(u32*)&v;
}
__device__ __forceinline__ float2 unpack_h2(u32 v) {
    return __half22float2(*(__half2*)&v);
}
__device__ __forceinline__ __half2 h2_of(u32 v) { return *(__half2*)&v; }
__device__ __forceinline__ u32 u_of(__half2 v) { return *(u32*)&v; }

// m16n8k16 fp16 in / fp16 accumulate
__device__ __forceinline__ void mma16816h(u32& c0, u32& c1,
                                          u32 a0, u32 a1, u32 a2, u32 a3,
                                          u32 b0, u32 b1) {
    asm("mma.sync.aligned.m16n8k16.row.col.f16.f16.f16.f16 "
        "{%0,%1}, {%2,%3,%4,%5}, {%6,%7}, {%0,%1};"
        : "+r"(c0), "+r"(c1)
        : "r"(a0), "r"(a1), "r"(a2), "r"(a3), "r"(b0), "r"(b1));
}

// ---------------------------------------------------------------------------
// Kernel 1: P2 via fp16 HMMA (R12 winning version, unchanged)
// ---------------------------------------------------------------------------
__global__ __launch_bounds__(256) void pbuild_kernel(
    const float* __restrict__ E,
    const float* __restrict__ Wx_f, const float* __restrict__ b_f,
    const float* __restrict__ Wx_b, const float* __restrict__ b_b)
{
    int dir = blockIdx.y;
    int r0  = blockIdx.x * PBR;
    const float* __restrict__ Wx = dir ? Wx_b : Wx_f;
    const float* __restrict__ bs = dir ? b_b : b_f;

    __shared__ __half es[PBR][EMB];
    __shared__ u32 zs[PBR][ZC / 2];

    int tid  = threadIdx.x;
    int w    = tid >> 5;
    int lane = tid & 31;
    int qr   = lane >> 2;
    int tl   = lane & 3;

    for (int i = tid; i < PBR * EMB; i += 256) {
        int r = i >> 6, e = i & 63;
        int row = r0 + r;
        int rc = (row < VOCAB) ? row : (VOCAB - 1);
        es[r][e] = __float2half(E[rc * EMB + e]);
    }

    u32 bfr[8][4][2];
#pragma unroll
    for (int nt = 0; nt < 8; nt++) {
        int n = 64 * w + 8 * nt + qr;
#pragma unroll
        for (int kt = 0; kt < 4; kt++) {
            int k0 = 16 * kt + 2 * tl;
            bfr[nt][kt][0] = pack_h2(Wx[k0 * ZC + n],       Wx[(k0 + 1) * ZC + n]);
            bfr[nt][kt][1] = pack_h2(Wx[(k0 + 8) * ZC + n], Wx[(k0 + 9) * ZC + n]);
        }
    }
    u32 binit[8];
#pragma unroll
    for (int nt = 0; nt < 8; nt++) {
        int c = 64 * w + 8 * nt + 2 * tl;
        binit[nt] = pack_h2(bs[c], bs[c + 1]);
    }
    __syncthreads();

#pragma unroll
    for (int mt = 0; mt < 2; mt++) {
        int rb = 16 * mt;
        u32 a[4][4];
#pragma unroll
        for (int kt = 0; kt < 4; kt++) {
            int k0 = 16 * kt + 2 * tl;
            a[kt][0] = *(const u32*)&es[rb + qr][k0];
            a[kt][1] = *(const u32*)&es[rb + 8 + qr][k0];
            a[kt][2] = *(const u32*)&es[rb + qr][k0 + 8];
            a[kt][3] = *(const u32*)&es[rb + 8 + qr][k0 + 8];
        }
#pragma unroll
        for (int nt = 0; nt < 8; nt++) {
            u32 c0 = binit[nt], c1 = binit[nt];
#pragma unroll
            for (int kt = 0; kt < 4; kt++)
                mma16816h(c0, c1, a[kt][0], a[kt][1], a[kt][2], a[kt][3],
                          bfr[nt][kt][0], bfr[nt][kt][1]);
            int cp = 32 * w + 4 * nt + tl;
            zs[rb + qr][cp]     = c0;
            zs[rb + 8 + qr][cp] = c1;
        }
    }
    __syncthreads();

    const __half* zh = (const __half*)zs;
    for (int i = tid; i < PBR * RNN; i += 256) {
        int r = i >> 7, u = i & 127;
        int row = r0 + r;
        if (row < VOCAB) {
            const __half* zr = zh + r * ZC;
            g_P2[dir][row][u] = make_uint2(
                u_of(__halves2half2(zr[u],       zr[u + 128])),
                u_of(__halves2half2(zr[u + 256], zr[u + 384])));
        }
    }
}

// ---------------------------------------------------------------------------
// Kernel 2: persistent LSTM (best-known fp16 HMMA version, unchanged).
// A = Wh^T fp16 regs, B = h fp16 smem (n=8 batch), fp16 acc, 4 chains/warp.
// ---------------------------------------------------------------------------
__global__ __launch_bounds__(512, 1) void lstm_kernel(
    const int* __restrict__ inputs,
    const float* __restrict__ Wh_f, const float* __restrict__ Wh_b)
{
    __shared__ __align__(16) u32 hA[512];
    __shared__ __align__(16) u32 hB[512];
    __shared__ __align__(8) int2 tok2_s[LL][4];

    int dir = blockIdx.x >> 6;
    int bi  = blockIdx.x & 63;
    int b0  = bi * G;
    const float* __restrict__ Wh = dir ? Wh_b : Wh_f;
    int tid  = threadIdx.x;
    int w    = tid >> 5;
    int lane = tid & 31;
    int gm   = lane >> 2;
    int tl   = lane & 3;

    for (int i = tid; i < 512; i += 512) { hA[i] = 0u; hB[i] = 0u; }
    for (int i = tid; i < 4 * LL; i += 512) {
        int t = i >> 2, pr = i & 3;
        tok2_s[t][pr] = make_int2(inputs[(b0 + 2 * pr) * LL + t],
                                  inputs[(b0 + 2 * pr + 1) * LL + t]);
    }

    int u = 8 * w + gm;

    u32 afr[2][8][4];
#pragma unroll
    for (int ti = 0; ti < 2; ti++) {
        int oA = (2 * ti) * 128 + u;
        int oB = oA + 128;
#pragma unroll
        for (int kc = 0; kc < 8; kc++) {
            int kb = 16 * kc + 2 * tl;
            afr[ti][kc][0] = pack_h2(Wh[kb * ZC + oA],       Wh[(kb + 1) * ZC + oA]);
            afr[ti][kc][1] = pack_h2(Wh[kb * ZC + oB],       Wh[(kb + 1) * ZC + oB]);
            afr[ti][kc][2] = pack_h2(Wh[(kb + 8) * ZC + oA], Wh[(kb + 9) * ZC + oA]);
            afr[ti][kc][3] = pack_h2(Wh[(kb + 8) * ZC + oB], Wh[(kb + 9) * ZC + oB]);
        }
    }
    __syncthreads();

    int be = 2 * tl;
    int j = u & 15, kch = u >> 4;
    int rr = (j >> 3) & 1, tlp = (j & 7) >> 1, half = j & 1;
    int hwE = ((kch * 64 + (be * 4 + tlp) * 2 + rr) << 1) + half;
    int hwO = hwE + 16;

    u32* stage = &g_hstage[dir][bi][0][0];

    int t0 = dir ? (LL - 1) : 0;
    int2 tk = tok2_s[t0][tl];
    uint2 pE = g_P2[dir][tk.x][u];
    uint2 pO = g_P2[dir][tk.y][u];

    float c0 = 0.0f, c1 = 0.0f;

    for (int step = 0; step < LL; step++) {
        int t = dir ? (LL - 1 - step) : step;
        const u32* rd = (step & 1) ? hB : hA;
        __half* wrh = (__half*)((step & 1) ? hA : hB);

        u32 cA[2][2], cB[2][2];
        {
            __half2 eif = h2_of(pE.x), oif = h2_of(pO.x);
            __half2 ego = h2_of(pE.y), ogo = h2_of(pO.y);
            cA[0][0] = u_of(__lows2half2(eif, oif));
            cA[0][1] = u_of(__highs2half2(eif, oif));
            cA[1][0] = u_of(__lows2half2(ego, ogo));
            cA[1][1] = u_of(__highs2half2(ego, ogo));
            cB[0][0] = cB[0][1] = cB[1][0] = cB[1][1] = 0u;
        }

        int tn = (step + 1 < LL) ? (dir ? t - 1 : t + 1) : t;
        tk = tok2_s[tn][tl];
        pE = g_P2[dir][tk.x][u];
        pO = g_P2[dir][tk.y][u];

#pragma unroll
        for (int kc = 0; kc < 4; kc++) {
            uint2 bb = *(const uint2*)&rd[kc * 64 + lane * 2];
            mma16816h(cA[0][0], cA[0][1],
                      afr[0][kc][0], afr[0][kc][1], afr[0][kc][2], afr[0][kc][3],
                      bb.x, bb.y);
            mma16816h(cA[1][0], cA[1][1],
                      afr[1][kc][0], afr[1][kc][1], afr[1][kc][2], afr[1][kc][3],
                      bb.x, bb.y);
            uint2 bb2 = *(const uint2*)&rd[(kc + 4) * 64 + lane * 2];
            mma16816h(cB[0][0], cB[0][1],
                      afr[0][kc + 4][0], afr[0][kc + 4][1], afr[0][kc + 4][2], afr[0][kc + 4][3],
                      bb2.x, bb2.y);
            mma16816h(cB[1][0], cB[1][1],
                      afr[1][kc + 4][0], afr[1][kc + 4][1], afr[1][kc + 4][2], afr[1][kc + 4][3],
                      bb2.x, bb2.y);
        }

        float2 zi = __half22float2(__hadd2(h2_of(cA[0][0]), h2_of(cB[0][0])));
        float2 zf = __half22float2(__hadd2(h2_of(cA[0][1]), h2_of(cB[0][1])));
        float2 zg = __half22float2(__hadd2(h2_of(cA[1][0]), h2_of(cB[1][0])));
        float2 zo = __half22float2(__hadd2(h2_of(cA[1][1]), h2_of(cB[1][1])));

        c0 = fast_sig(zf.x) * c0 + fast_sig(zi.x) * fast_tanh(zg.x);
        float hE = fast_sig(zo.x) * fast_tanh(c0);
        c1 = fast_sig(zf.y) * c1 + fast_sig(zi.y) * fast_tanh(zg.y);
        float hO = fast_sig(zo.y) * fast_tanh(c1);

        wrh[hwE] = __float2half(hE);
        wrh[hwO] = __float2half(hO);
        stage[t * 512 + tid] = pack_h2(hE, hO);
        __syncthreads();
    }
}

// ---------------------------------------------------------------------------
// Kernel 3: logits (unchanged)
// ---------------------------------------------------------------------------
__global__ __launch_bounds__(512) void logits_kernel(
    const float* __restrict__ Wd, const float* __restrict__ bd)
{
    __shared__ __align__(16) float h_s[LR][2 * RNN];
    __shared__ __align__(16) float2 Wt2[KK][RNN + 1];
    __shared__ float bd_s[KK];

    int tid = threadIdx.x;
    int bt0 = blockIdx.x * LR;

    for (int i = tid; i < KK * RNN; i += 512) {
        int k = i / RNN, e2 = i % RNN;
        Wt2[k][e2] = make_float2(Wd[(2 * e2) * KK + k], Wd[(2 * e2 + 1) * KK + k]);
    }
    if (tid < KK) bd_s[tid] = bd[tid];
    for (int i = tid; i < LR * 2 * RNN; i += 512) {
        int r = i >> 8, e = i & 255;
        int bt = bt0 + r;
        if (bt < BB * LL) {
            int b = bt >> 8, t = bt & 255;
            int dir = e >> 7, uu = e & 127;
            u32 v = g_hstage[dir][b >> 3][t][(uu >> 3) * 32 + (uu & 7) * 4 + ((b & 7) >> 1)];
            float2 hv = unpack_h2(v);
            h_s[r][e] = (b & 1) ? hv.y : hv.x;
        }
    }
    __syncthreads();

    if (tid >= LR * KK) return;
    int r = tid / KK, k = tid % KK;
    int bt = bt0 + r;
    if (bt >= BB * LL) return;

    u64 acc = 0;
    const u64* hp = (const u64*)&h_s[r][0];
    const u64* wp = (const u64*)&Wt2[k][0];
#pragma unroll 8
    for (int e2 = 0; e2 < RNN; e2++) ffma2(acc, hp[e2], wp[e2]);

    float lo, hi; upk2(acc, lo, hi);
    int b = bt >> 8, t = bt & 255;
    g_logits[b][t][k] = lo + hi + bd_s[k];
}

// ---------------------------------------------------------------------------
// Kernel 4: CRF — reverted to the proven 57us shape (1 row/warp, 128-thr
// blocks, 129 blocks) with ONE change: 3-way tree split of the 18-term sum
// (serial chain 18 FMA -> 6 FMA + 2 ADD). expT trick + logit prefetch kept.
// ---------------------------------------------------------------------------
__global__ __launch_bounds__(128) void crf_kernel(
    const int* __restrict__ labels, const float* __restrict__ T,
    float* __restrict__ out, int out_size)
{
    if (blockIdx.x == BB / 4) {
        for (int i = threadIdx.x; i < KK * KK; i += 128)
            if ((BB + i) < out_size) out[BB + i] = T[i];
        return;
    }

    __shared__ float T_s[KK * KK];
    __shared__ float expT_s[KK][KK];
    int tid = threadIdx.x;
    for (int i = tid; i < KK * KK; i += 128) {
        float tv = T[i];
        T_s[i] = tv;
        expT_s[i / KK][i % KK] = __expf(tv);
    }
    __syncthreads();

    int warp = tid >> 5;
    int lane = tid & 31;
    int b = blockIdx.x * 4 + warp;
    if (b >= BB) return;

    const int* lab = labels + b * LL;

    int cnt = 0;
    for (int l = lane; l < LL; l += 32) cnt += (lab[l] != 0);
#pragma unroll
    for (int off = 16; off; off >>= 1) cnt += __shfl_xor_sync(0xffffffffu, cnt, off);
    int len = cnt;

    float us = 0.0f, bs = 0.0f;
    for (int l = lane; l < LL; l += 32) {
        int y = lab[l];
        if (l < len) us += g_logits[b][l][y];
        if (l >= 1 && l < len) bs += T_s[lab[l - 1] * KK + y];
    }
#pragma unroll
    for (int off = 16; off; off >>= 1) {
        us += __shfl_xor_sync(0xffffffffu, us, off);
        bs += __shfl_xor_sync(0xffffffffu, bs, off);
    }

    int k = (lane < KK) ? lane : 0;
    float alpha = (lane < KK) ? g_logits[b][0][k] : -1e30f;
    float lg = g_logits[b][1][k];        // prefetched logit row
    for (int l = 1; l < LL; l++) {
        float lg_next = (l + 1 < LL) ? g_logits[b][l + 1][k] : 0.0f;
        float a0 = __shfl_sync(0xffffffffu, alpha, 0);
        float e = (lane < KK) ? __expf(alpha - a0) : 0.0f;
        float s0 = 0.f, s1 = 0.f, s2 = 0.f;
#pragma unroll
        for (int k1 = 0; k1 < 6; k1++) {
            s0 = fmaf(__shfl_sync(0xffffffffu, e, k1),      expT_s[k1][k],      s0);
            s1 = fmaf(__shfl_sync(0xffffffffu, e, k1 + 6),  expT_s[k1 + 6][k],  s1);
            s2 = fmaf(__shfl_sync(0xffffffffu, e, k1 + 12), expT_s[k1 + 12][k], s2);
        }
        float na = a0 + __logf((s0 + s1) + s2) + lg;
        if (lane < KK && l < len) alpha = na;
        lg = lg_next;
    }

    float m = alpha;
#pragma unroll
    for (int off = 16; off; off >>= 1) m = fmaxf(m, __shfl_xor_sync(0xffffffffu, m, off));
    float es = (lane < KK) ? __expf(alpha - m) : 0.0f;
#pragma unroll
    for (int off = 16; off; off >>= 1) es += __shfl_xor_sync(0xffffffffu, es, off);
    float lse = m + __logf(es);

    if (lane == 0 && b < out_size) out[b] = us + bs - lse;
}

// ---------------------------------------------------------------------------
extern "C" void kernel_launch(void* const* d_in, const int* in_sizes, int n_in,
                              void* d_out, int out_size)
{
    const int*   inputs = (const int*)  d_in[0];
    const int*   labels = (const int*)  d_in[1];
    const float* E      = (const float*)d_in[2];
    const float* Wx_f   = (const float*)d_in[3];
    const float* Wh_f   = (const float*)d_in[4];
    const float* b_f    = (const float*)d_in[5];
    const float* Wx_b   = (const float*)d_in[6];
    const float* Wh_b   = (const float*)d_in[7];
    const float* b_b    = (const float*)d_in[8];
    const float* Wd     = (const float*)d_in[9];
    const float* bd     = (const float*)d_in[10];
    const float* T      = (const float*)d_in[11];
    float* out = (float*)d_out;

    dim3 pg((VOCAB + PBR - 1) / PBR, 2);
    pbuild_kernel<<<pg, 256>>>(E, Wx_f, b_f, Wx_b, b_b);
    lstm_kernel<<<128, 512>>>(inputs, Wh_f, Wh_b);
    int nbt = BB * LL;
    logits_kernel<<<(nbt + LR - 1) / LR, 512>>>(Wd, bd);
    crf_kernel<<<BB / 4 + 1, 128>>>(labels, T, out, out_size);
}

// round 15
// speedup vs baseline: 1.7188x; 1.3249x over previous
#include <cuda_runtime.h>
#include <cuda_fp16.h>
#include <math.h>

#define EMB 64
#define RNN 128
#define BB  512
#define LL  256
#define KK  18
#define G   8
#define ZC  512   // 4*RNN
#define VOCAB 30001
#define PBR 32    // vocab rows per pbuild block
#define LB  64    // (b,t) rows per logits block
#define HSP 264   // padded half-row (2*RNN + 8) to avoid qr bank conflicts

// Scratch (static device allocations; no cudaMalloc allowed)
__device__ uint2 g_P2[2][VOCAB][RNN];                 // ~61 MB (L2-resident)
__device__ unsigned int g_hstage[2][BB / G][LL][512]; // coalesced writes
__device__ float g_logits[BB][LL][KK];

typedef unsigned long long u64;
typedef unsigned int u32;

__device__ __forceinline__ u64 pk2(float lo, float hi) {
    u64 r; asm("mov.b64 %0,{%1,%2};" : "=l"(r) : "f"(lo), "f"(hi)); return r;
}
__device__ __forceinline__ void upk2(u64 v, float& lo, float& hi) {
    asm("mov.b64 {%0,%1},%2;" : "=f"(lo), "=f"(hi) : "l"(v));
}
__device__ __forceinline__ float fast_tanh(float x) {
    float y; asm("tanh.approx.f32 %0, %1;" : "=f"(y) : "f"(x)); return y;
}
__device__ __forceinline__ u32 pack_h2(float lo, float hi) {
    __half2 v = __floats2half2_rn(lo, hi);
    return *(u32*)&v;
}
__device__ __forceinline__ float2 unpack_h2(u32 v) {
    return __half22float2(*(__half2*)&v);
}
__device__ __forceinline__ __half2 h2_of(u32 v) { return *(__half2*)&v; }
__device__ __forceinline__ u32 u_of(__half2 v) { return *(u32*)&v; }
__device__ __forceinline__ u32 h2tanh_u(u32 x) {
    u32 y; asm("tanh.approx.f16x2 %0, %1;" : "=r"(y) : "r"(x)); return y;
}
__device__ __forceinline__ u32 h2sig_u(u32 x) {
    // sig(x) = 0.5*tanh(0.5x) + 0.5, packed
    __half2 h05 = __floats2half2_rn(0.5f, 0.5f);
    __half2 t = h2_of(h2tanh_u(u_of(__hmul2(h2_of(x), h05))));
    return u_of(__hfma2(t, h05, h05));
}

// m16n8k16 fp16 in / fp16 accumulate
__device__ __forceinline__ void mma16816h(u32& c0, u32& c1,
                                          u32 a0, u32 a1, u32 a2, u32 a3,
                                          u32 b0, u32 b1) {
    asm("mma.sync.aligned.m16n8k16.row.col.f16.f16.f16.f16 "
        "{%0,%1}, {%2,%3,%4,%5}, {%6,%7}, {%0,%1};"
        : "+r"(c0), "+r"(c1)
        : "r"(a0), "r"(a1), "r"(a2), "r"(a3), "r"(b0), "r"(b1));
}
// m16n8k16 fp16 in / fp32 accumulate (logits)
__device__ __forceinline__ void mma16816f(float& d0, float& d1, float& d2, float& d3,
                                          u32 a0, u32 a1, u32 a2, u32 a3,
                                          u32 b0, u32 b1) {
    asm("mma.sync.aligned.m16n8k16.row.col.f32.f16.f16.f32 "
        "{%0,%1,%2,%3}, {%4,%5,%6,%7}, {%8,%9}, {%0,%1,%2,%3};"
        : "+f"(d0), "+f"(d1), "+f"(d2), "+f"(d3)
        : "r"(a0), "r"(a1), "r"(a2), "r"(a3), "r"(b0), "r"(b1));
}

// ---------------------------------------------------------------------------
// Kernel 1: P2 via fp16 HMMA (unchanged winning version)
// ---------------------------------------------------------------------------
__global__ __launch_bounds__(256) void pbuild_kernel(
    const float* __restrict__ E,
    const float* __restrict__ Wx_f, const float* __restrict__ b_f,
    const float* __restrict__ Wx_b, const float* __restrict__ b_b)
{
    int dir = blockIdx.y;
    int r0  = blockIdx.x * PBR;
    const float* __restrict__ Wx = dir ? Wx_b : Wx_f;
    const float* __restrict__ bs = dir ? b_b : b_f;

    __shared__ __half es[PBR][EMB];
    __shared__ u32 zs[PBR][ZC / 2];

    int tid  = threadIdx.x;
    int w    = tid >> 5;
    int lane = tid & 31;
    int qr   = lane >> 2;
    int tl   = lane & 3;

    for (int i = tid; i < PBR * EMB; i += 256) {
        int r = i >> 6, e = i & 63;
        int row = r0 + r;
        int rc = (row < VOCAB) ? row : (VOCAB - 1);
        es[r][e] = __float2half(E[rc * EMB + e]);
    }

    u32 bfr[8][4][2];
#pragma unroll
    for (int nt = 0; nt < 8; nt++) {
        int n = 64 * w + 8 * nt + qr;
#pragma unroll
        for (int kt = 0; kt < 4; kt++) {
            int k0 = 16 * kt + 2 * tl;
            bfr[nt][kt][0] = pack_h2(Wx[k0 * ZC + n],       Wx[(k0 + 1) * ZC + n]);
            bfr[nt][kt][1] = pack_h2(Wx[(k0 + 8) * ZC + n], Wx[(k0 + 9) * ZC + n]);
        }
    }
    u32 binit[8];
#pragma unroll
    for (int nt = 0; nt < 8; nt++) {
        int c = 64 * w + 8 * nt + 2 * tl;
        binit[nt] = pack_h2(bs[c], bs[c + 1]);
    }
    __syncthreads();

#pragma unroll
    for (int mt = 0; mt < 2; mt++) {
        int rb = 16 * mt;
        u32 a[4][4];
#pragma unroll
        for (int kt = 0; kt < 4; kt++) {
            int k0 = 16 * kt + 2 * tl;
            a[kt][0] = *(const u32*)&es[rb + qr][k0];
            a[kt][1] = *(const u32*)&es[rb + 8 + qr][k0];
            a[kt][2] = *(const u32*)&es[rb + qr][k0 + 8];
            a[kt][3] = *(const u32*)&es[rb + 8 + qr][k0 + 8];
        }
#pragma unroll
        for (int nt = 0; nt < 8; nt++) {
            u32 c0 = binit[nt], c1 = binit[nt];
#pragma unroll
            for (int kt = 0; kt < 4; kt++)
                mma16816h(c0, c1, a[kt][0], a[kt][1], a[kt][2], a[kt][3],
                          bfr[nt][kt][0], bfr[nt][kt][1]);
            int cp = 32 * w + 4 * nt + tl;
            zs[rb + qr][cp]     = c0;
            zs[rb + 8 + qr][cp] = c1;
        }
    }
    __syncthreads();

    const __half* zh = (const __half*)zs;
    for (int i = tid; i < PBR * RNN; i += 256) {
        int r = i >> 7, u = i & 127;
        int row = r0 + r;
        if (row < VOCAB) {
            const __half* zr = zh + r * ZC;
            g_P2[dir][row][u] = make_uint2(
                u_of(__halves2half2(zr[u],       zr[u + 128])),
                u_of(__halves2half2(zr[u + 256], zr[u + 384])));
        }
    }
}

// ---------------------------------------------------------------------------
// Kernel 2: persistent LSTM (fp16 HMMA, packed f16x2 gate activations)
// ---------------------------------------------------------------------------
__global__ __launch_bounds__(512, 1) void lstm_kernel(
    const int* __restrict__ inputs,
    const float* __restrict__ Wh_f, const float* __restrict__ Wh_b)
{
    __shared__ __align__(16) u32 hA[512];
    __shared__ __align__(16) u32 hB[512];
    __shared__ __align__(8) int2 tok2_s[LL][4];

    int dir = blockIdx.x >> 6;
    int bi  = blockIdx.x & 63;
    int b0  = bi * G;
    const float* __restrict__ Wh = dir ? Wh_b : Wh_f;
    int tid  = threadIdx.x;
    int w    = tid >> 5;
    int lane = tid & 31;
    int gm   = lane >> 2;
    int tl   = lane & 3;

    for (int i = tid; i < 512; i += 512) { hA[i] = 0u; hB[i] = 0u; }
    for (int i = tid; i < 4 * LL; i += 512) {
        int t = i >> 2, pr = i & 3;
        tok2_s[t][pr] = make_int2(inputs[(b0 + 2 * pr) * LL + t],
                                  inputs[(b0 + 2 * pr + 1) * LL + t]);
    }

    int u = 8 * w + gm;

    u32 afr[2][8][4];
#pragma unroll
    for (int ti = 0; ti < 2; ti++) {
        int oA = (2 * ti) * 128 + u;
        int oB = oA + 128;
#pragma unroll
        for (int kc = 0; kc < 8; kc++) {
            int kb = 16 * kc + 2 * tl;
            afr[ti][kc][0] = pack_h2(Wh[kb * ZC + oA],       Wh[(kb + 1) * ZC + oA]);
            afr[ti][kc][1] = pack_h2(Wh[kb * ZC + oB],       Wh[(kb + 1) * ZC + oB]);
            afr[ti][kc][2] = pack_h2(Wh[(kb + 8) * ZC + oA], Wh[(kb + 9) * ZC + oA]);
            afr[ti][kc][3] = pack_h2(Wh[(kb + 8) * ZC + oB], Wh[(kb + 9) * ZC + oB]);
        }
    }
    __syncthreads();

    int be = 2 * tl;
    int j = u & 15, kch = u >> 4;
    int rr = (j >> 3) & 1, tlp = (j & 7) >> 1, half = j & 1;
    int hwE = ((kch * 64 + (be * 4 + tlp) * 2 + rr) << 1) + half;
    int hwO = hwE + 16;

    u32* stage = &g_hstage[dir][bi][0][0];

    int t0 = dir ? (LL - 1) : 0;
    int2 tk = tok2_s[t0][tl];
    uint2 pE = g_P2[dir][tk.x][u];
    uint2 pO = g_P2[dir][tk.y][u];

    float c0 = 0.0f, c1 = 0.0f;

    for (int step = 0; step < LL; step++) {
        int t = dir ? (LL - 1 - step) : step;
        const u32* rd = (step & 1) ? hB : hA;
        __half* wrh = (__half*)((step & 1) ? hA : hB);

        u32 cA[2][2], cB[2][2];
        {
            __half2 eif = h2_of(pE.x), oif = h2_of(pO.x);
            __half2 ego = h2_of(pE.y), ogo = h2_of(pO.y);
            cA[0][0] = u_of(__lows2half2(eif, oif));
            cA[0][1] = u_of(__highs2half2(eif, oif));
            cA[1][0] = u_of(__lows2half2(ego, ogo));
            cA[1][1] = u_of(__highs2half2(ego, ogo));
            cB[0][0] = cB[0][1] = cB[1][0] = cB[1][1] = 0u;
        }

        int tn = (step + 1 < LL) ? (dir ? t - 1 : t + 1) : t;
        tk = tok2_s[tn][tl];
        pE = g_P2[dir][tk.x][u];
        pO = g_P2[dir][tk.y][u];

#pragma unroll
        for (int kc = 0; kc < 4; kc++) {
            uint2 bb = *(const uint2*)&rd[kc * 64 + lane * 2];
            mma16816h(cA[0][0], cA[0][1],
                      afr[0][kc][0], afr[0][kc][1], afr[0][kc][2], afr[0][kc][3],
                      bb.x, bb.y);
            mma16816h(cA[1][0], cA[1][1],
                      afr[1][kc][0], afr[1][kc][1], afr[1][kc][2], afr[1][kc][3],
                      bb.x, bb.y);
            uint2 bb2 = *(const uint2*)&rd[(kc + 4) * 64 + lane * 2];
            mma16816h(cB[0][0], cB[0][1],
                      afr[0][kc + 4][0], afr[0][kc + 4][1], afr[0][kc + 4][2], afr[0][kc + 4][3],
                      bb2.x, bb2.y);
            mma16816h(cB[1][0], cB[1][1],
                      afr[1][kc + 4][0], afr[1][kc + 4][1], afr[1][kc + 4][2], afr[1][kc + 4][3],
                      bb2.x, bb2.y);
        }

        // packed gate activations (tanh.approx.f16x2), fp32 c recurrence
        u32 zi_u = u_of(__hadd2(h2_of(cA[0][0]), h2_of(cB[0][0])));
        u32 zf_u = u_of(__hadd2(h2_of(cA[0][1]), h2_of(cB[0][1])));
        u32 zg_u = u_of(__hadd2(h2_of(cA[1][0]), h2_of(cB[1][0])));
        u32 zo_u = u_of(__hadd2(h2_of(cA[1][1]), h2_of(cB[1][1])));
        float2 si = unpack_h2(h2sig_u(zi_u));
        float2 sf = unpack_h2(h2sig_u(zf_u));
        float2 tg = unpack_h2(h2tanh_u(zg_u));
        float2 so = unpack_h2(h2sig_u(zo_u));

        c0 = sf.x * c0 + si.x * tg.x;
        float hE = so.x * fast_tanh(c0);
        c1 = sf.y * c1 + si.y * tg.y;
        float hO = so.y * fast_tanh(c1);

        wrh[hwE] = __float2half(hE);
        wrh[hwO] = __float2half(hO);
        stage[t * 512 + tid] = pack_h2(hE, hO);
        __syncthreads();
    }
}

// ---------------------------------------------------------------------------
// Kernel 3: logits via fp16 HMMA, fp32 accumulate.
// Block = 128 thr (4 warps), 64 (b,t) rows; warp = one m16 tile of rows.
// A = h rows (padded smem fp16), B = Wd^T padded to n=24 (3 n-tiles).
// ---------------------------------------------------------------------------
__global__ __launch_bounds__(128) void logits_kernel(
    const float* __restrict__ Wd, const float* __restrict__ bd)
{
    __shared__ __half hs[LB][HSP];      // h rows (padded: qr-conflict-free)
    __shared__ __half wdt[24][HSP];     // Wd^T, n-padded with zeros
    __shared__ float bd_s[24];

    int tid  = threadIdx.x;
    int w    = tid >> 5;
    int lane = tid & 31;
    int qr   = lane >> 2;
    int tl   = lane & 3;
    int bt0  = blockIdx.x * LB;

    for (int i = tid; i < 24 * 256; i += 128) {
        int n = i >> 8, kx = i & 255;
        wdt[n][kx] = (n < KK) ? __float2half(Wd[kx * KK + n]) : __ushort_as_half(0);
    }
    if (tid < 24) bd_s[tid] = (tid < KK) ? bd[tid] : 0.0f;

    for (int i = tid; i < LB * 256; i += 128) {
        int r = i >> 8, e = i & 255;
        int bt = bt0 + r;
        int b = bt >> 8, t = bt & 255;
        int dir = e >> 7, uu = e & 127;
        u32 v = g_hstage[dir][b >> 3][t][(uu >> 3) * 32 + (uu & 7) * 4 + ((b & 7) >> 1)];
        __half2 hh = h2_of(v);
        hs[r][e] = (b & 1) ? __high2half(hh) : __low2half(hh);
    }
    __syncthreads();

    int r0w = w * 16;

    // B fragments (from smem; same conventions as pbuild)
    u32 bfr[3][16][2];
#pragma unroll
    for (int nt = 0; nt < 3; nt++) {
        int n = 8 * nt + qr;
#pragma unroll
        for (int kt = 0; kt < 16; kt++) {
            int k0 = 16 * kt + 2 * tl;
            bfr[nt][kt][0] = *(const u32*)&wdt[n][k0];
            bfr[nt][kt][1] = *(const u32*)&wdt[n][k0 + 8];
        }
    }

    float d[3][4];
#pragma unroll
    for (int nt = 0; nt < 3; nt++) {
        float blo = bd_s[8 * nt + 2 * tl], bhi = bd_s[8 * nt + 2 * tl + 1];
        d[nt][0] = blo; d[nt][1] = bhi; d[nt][2] = blo; d[nt][3] = bhi;
    }

#pragma unroll
    for (int kt = 0; kt < 16; kt++) {
        int k0 = 16 * kt + 2 * tl;
        u32 a0 = *(const u32*)&hs[r0w + qr][k0];
        u32 a1 = *(const u32*)&hs[r0w + 8 + qr][k0];
        u32 a2 = *(const u32*)&hs[r0w + qr][k0 + 8];
        u32 a3 = *(const u32*)&hs[r0w + 8 + qr][k0 + 8];
#pragma unroll
        for (int nt = 0; nt < 3; nt++)
            mma16816f(d[nt][0], d[nt][1], d[nt][2], d[nt][3],
                      a0, a1, a2, a3, bfr[nt][kt][0], bfr[nt][kt][1]);
    }

    int btA = bt0 + r0w + qr, btB = btA + 8;
    int bA = btA >> 8, tA = btA & 255;
    int bBv = btB >> 8, tB = btB & 255;
#pragma unroll
    for (int nt = 0; nt < 3; nt++) {
        int kc = 8 * nt + 2 * tl;
        if (kc < KK) {
            g_logits[bA][tA][kc]  = d[nt][0];
            g_logits[bBv][tB][kc] = d[nt][2];
        }
        if (kc + 1 < KK) {
            g_logits[bA][tA][kc + 1]  = d[nt][1];
            g_logits[bBv][tB][kc + 1] = d[nt][3];
        }
    }
}

// ---------------------------------------------------------------------------
// Kernel 4: CRF (proven shape) with prefetch depth 2 (hides L2 latency
// behind two ~150-cyc chains). Tree-split sum, expT trick.
// ---------------------------------------------------------------------------
__global__ __launch_bounds__(128) void crf_kernel(
    const int* __restrict__ labels, const float* __restrict__ T,
    float* __restrict__ out, int out_size)
{
    if (blockIdx.x == BB / 4) {
        for (int i = threadIdx.x; i < KK * KK; i += 128)
            if ((BB + i) < out_size) out[BB + i] = T[i];
        return;
    }

    __shared__ float T_s[KK * KK];
    __shared__ float expT_s[KK][KK];
    int tid = threadIdx.x;
    for (int i = tid; i < KK * KK; i += 128) {
        float tv = T[i];
        T_s[i] = tv;
        expT_s[i / KK][i % KK] = __expf(tv);
    }
    __syncthreads();

    int warp = tid >> 5;
    int lane = tid & 31;
    int b = blockIdx.x * 4 + warp;
    if (b >= BB) return;

    const int* lab = labels + b * LL;

    int cnt = 0;
    for (int l = lane; l < LL; l += 32) cnt += (lab[l] != 0);
#pragma unroll
    for (int off = 16; off; off >>= 1) cnt += __shfl_xor_sync(0xffffffffu, cnt, off);
    int len = cnt;

    float us = 0.0f, bs = 0.0f;
    for (int l = lane; l < LL; l += 32) {
        int y = lab[l];
        if (l < len) us += g_logits[b][l][y];
        if (l >= 1 && l < len) bs += T_s[lab[l - 1] * KK + y];
    }
#pragma unroll
    for (int off = 16; off; off >>= 1) {
        us += __shfl_xor_sync(0xffffffffu, us, off);
        bs += __shfl_xor_sync(0xffffffffu, bs, off);
    }

    int k = (lane < KK) ? lane : 0;
    float alpha = (lane < KK) ? g_logits[b][0][k] : -1e30f;
    float lg0 = g_logits[b][1][k];
    float lg1 = g_logits[b][2][k];
    for (int l = 1; l < LL; l++) {
        float lgn = (l + 2 < LL) ? g_logits[b][l + 2][k] : 0.0f;
        float a0 = __shfl_sync(0xffffffffu, alpha, 0);
        float e = (lane < KK) ? __expf(alpha - a0) : 0.0f;
        float s0 = 0.f, s1 = 0.f, s2 = 0.f;
#pragma unroll
        for (int k1 = 0; k1 < 6; k1++) {
            s0 = fmaf(__shfl_sync(0xffffffffu, e, k1),      expT_s[k1][k],      s0);
            s1 = fmaf(__shfl_sync(0xffffffffu, e, k1 + 6),  expT_s[k1 + 6][k],  s1);
            s2 = fmaf(__shfl_sync(0xffffffffu, e, k1 + 12), expT_s[k1 + 12][k], s2);
        }
        float na = a0 + __logf((s0 + s1) + s2) + lg0;
        if (lane < KK && l < len) alpha = na;
        lg0 = lg1;
        lg1 = lgn;
    }

    float m = alpha;
#pragma unroll
    for (int off = 16; off; off >>= 1) m = fmaxf(m, __shfl_xor_sync(0xffffffffu, m, off));
    float es = (lane < KK) ? __expf(alpha - m) : 0.0f;
#pragma unroll
    for (int off = 16; off; off >>= 1) es += __shfl_xor_sync(0xffffffffu, es, off);
    float lse = m + __logf(es);

    if (lane == 0 && b < out_size) out[b] = us + bs - lse;
}

// ---------------------------------------------------------------------------
extern "C" void kernel_launch(void* const* d_in, const int* in_sizes, int n_in,
                              void* d_out, int out_size)
{
    const int*   inputs = (const int*)  d_in[0];
    const int*   labels = (const int*)  d_in[1];
    const float* E      = (const float*)d_in[2];
    const float* Wx_f   = (const float*)d_in[3];
    const float* Wh_f   = (const float*)d_in[4];
    const float* b_f    = (const float*)d_in[5];
    const float* Wx_b   = (const float*)d_in[6];
    const float* Wh_b   = (const float*)d_in[7];
    const float* b_b    = (const float*)d_in[8];
    const float* Wd     = (const float*)d_in[9];
    const float* bd     = (const float*)d_in[10];
    const float* T      = (const float*)d_in[11];
    float* out = (float*)d_out;

    dim3 pg((VOCAB + PBR - 1) / PBR, 2);
    pbuild_kernel<<<pg, 256>>>(E, Wx_f, b_f, Wx_b, b_b);
    lstm_kernel<<<128, 512>>>(inputs, Wh_f, Wh_b);
    logits_kernel<<<(BB * LL) / LB, 128>>>(Wd, bd);
    crf_kernel<<<BB / 4 + 1, 128>>>(labels, T, out, out_size);
}